// round 2
// baseline (speedup 1.0000x reference)
#include <cuda_runtime.h>

// Problem constants (fixed shapes from reference)
#define N_TOK 5120     // T*H*W = 5*32*32
#define FDIM  10
#define FP    12       // padded q row stride (float4 aligned)
#define KVZ   24       // packed row: k[10],pad[2],v[10],zinv,pad
#define C_DIM 64
#define HW    1024
#define OUT_ELEMS 51200

// Scratch (allocation-free: device globals)
__device__ float g_q[N_TOK * FP];     // [n][12]: q0..q9, 0, 0
__device__ float g_kvz[N_TOK * KVZ];  // [m][24]: k0..k9,0,0, v0..v9, zinv, (unused)
__device__ float g_Z[N_TOK];          // column sums of exp(scores)

#define SPLA 16   // n-splits for column-sum kernel
#define SPLB 32   // m-splits for attention kernel

// ---------------------------------------------------------------------------
__global__ void k_init(float* __restrict__ out) {
    int i = blockIdx.x * blockDim.x + threadIdx.x;
    if (i < N_TOK)     g_Z[i] = 0.f;
    if (i < OUT_ELEMS) out[i] = 0.f;
}

// ---------------------------------------------------------------------------
// Pointwise conv projections: q,v from input1, k from input2.
// One thread per token n. Weights broadcast from shared.
__global__ void k_proj(const float* __restrict__ in1, const float* __restrict__ in2,
                       const float* __restrict__ w1, const float* __restrict__ b1,
                       const float* __restrict__ w2, const float* __restrict__ b2,
                       const float* __restrict__ w3, const float* __restrict__ b3) {
    __shared__ float sw1[FDIM * C_DIM], sw2[FDIM * C_DIM], sw3[FDIM * C_DIM];
    int tid = threadIdx.x;
    for (int i = tid; i < FDIM * C_DIM; i += 256) {
        sw1[i] = w1[i]; sw2[i] = w2[i]; sw3[i] = w3[i];
    }
    __syncthreads();

    int n  = blockIdx.x * 256 + tid;
    int t  = n >> 10;
    int hw = n & 1023;
    const float* p1 = in1 + t * (C_DIM * HW) + hw;
    const float* p2 = in2 + t * (C_DIM * HW) + hw;

    float qa[FDIM], ka[FDIM], va[FDIM];
#pragma unroll
    for (int f = 0; f < FDIM; f++) { qa[f] = __ldg(b1 + f); ka[f] = __ldg(b2 + f); va[f] = __ldg(b3 + f); }

    for (int c = 0; c < C_DIM; c++) {
        float x1 = __ldg(p1 + c * HW);
        float x2 = __ldg(p2 + c * HW);
#pragma unroll
        for (int f = 0; f < FDIM; f++) {
            qa[f] = fmaf(sw1[f * C_DIM + c], x1, qa[f]);
            ka[f] = fmaf(sw2[f * C_DIM + c], x2, ka[f]);
            va[f] = fmaf(sw3[f * C_DIM + c], x1, va[f]);
        }
    }

    float* qrow = g_q   + n * FP;
    float* krow = g_kvz + n * KVZ;
#pragma unroll
    for (int f = 0; f < FDIM; f++) {
        qrow[f]      = qa[f];
        krow[f]      = ka[f];
        krow[12 + f] = va[f];
    }
    qrow[10] = 0.f; qrow[11] = 0.f;
    krow[10] = 0.f; krow[11] = 0.f;
}

// ---------------------------------------------------------------------------
__device__ __forceinline__ float dot10(float4 a0, float4 a1, float4 a2,
                                       float4 b0, float4 b1, float4 b2) {
    float s = a0.x * b0.x;
    s = fmaf(a0.y, b0.y, s);
    s = fmaf(a0.z, b0.z, s);
    s = fmaf(a0.w, b0.w, s);
    s = fmaf(a1.x, b1.x, s);
    s = fmaf(a1.y, b1.y, s);
    s = fmaf(a1.z, b1.z, s);
    s = fmaf(a1.w, b1.w, s);
    s = fmaf(a2.x, b2.x, s);
    s = fmaf(a2.y, b2.y, s);
    return s;
}

// Pass A: Z[m] = sum_n exp(q_n . k_m). Thread owns m, loops an n-slice.
__global__ void k_colsum(void) {
    int m = blockIdx.x * 256 + threadIdx.x;
    const float4* kp = (const float4*)(g_kvz + m * KVZ);
    float4 k0 = kp[0], k1 = kp[1], k2 = kp[2];

    int n0 = blockIdx.y * (N_TOK / SPLA);
    float z0 = 0.f, z1 = 0.f, z2 = 0.f, z3 = 0.f;
    float zacc[4] = {0.f, 0.f, 0.f, 0.f};
    for (int n = n0; n < n0 + N_TOK / SPLA; n += 4) {
#pragma unroll
        for (int u = 0; u < 4; u++) {
            const float4* qp = (const float4*)(g_q + (n + u) * FP);
            float4 q0 = __ldg(qp), q1 = __ldg(qp + 1), q2 = __ldg(qp + 2);
            float s = dot10(q0, q1, q2, k0, k1, k2);
            zacc[u] += __expf(s);
        }
    }
    z0 = zacc[0]; z1 = zacc[1]; z2 = zacc[2]; z3 = zacc[3];
    atomicAdd(&g_Z[m], (z0 + z1) + (z2 + z3));
}

// zinv[m] = w0 / Z[m], packed into g_kvz for single-stream loads in pass B.
__global__ void k_zinv(const float* __restrict__ aw) {
    int m = blockIdx.x * 256 + threadIdx.x;
    if (m < N_TOK) g_kvz[m * KVZ + 22] = __ldg(aw) / g_Z[m];
}

// ---------------------------------------------------------------------------
// Pass B: fused relu/sigmoid/softmax branches.
// Each thread owns 2 consecutive n, loops an m-slice; all threads in a warp
// share the same m each iteration -> broadcast LDG.128 of the packed kvz row.
__global__ void k_attn(const float* __restrict__ aw, float* __restrict__ out) {
    int tid = threadIdx.x;
    int n   = blockIdx.x * 512 + tid * 2;
    float w0 = __ldg(aw);
    float w1 = __ldg(aw + 1);

    const float4* qp = (const float4*)(g_q + n * FP);
    float4 qa0 = qp[0], qa1 = qp[1], qa2 = qp[2];
    float4 qb0 = qp[3], qb1 = qp[4], qb2 = qp[5];

    float acc0[FDIM], acc1[FDIM];
#pragma unroll
    for (int f = 0; f < FDIM; f++) { acc0[f] = 0.f; acc1[f] = 0.f; }

    int m0 = blockIdx.y * (N_TOK / SPLB);
    for (int m = m0; m < m0 + N_TOK / SPLB; m++) {
        const float4* kv = (const float4*)(g_kvz + m * KVZ);
        float4 k0 = __ldg(kv),     k1 = __ldg(kv + 1), k2 = __ldg(kv + 2);
        float4 v0 = __ldg(kv + 3), v1 = __ldg(kv + 4), v2 = __ldg(kv + 5);
        float zinv = v2.z;

        float sa = dot10(qa0, qa1, qa2, k0, k1, k2);
        float sb = dot10(qb0, qb1, qb2, k0, k1, k2);

        float ea = __expf(sa);
        float eb = __expf(sb);
        // coef = w0*relu(s) + w1*sigmoid(s) + (w0/Z[m])*exp(s); sigmoid(s)=e/(1+e)
        float ca = fmaf(w0, fmaxf(sa, 0.f), fmaf(w1, __fdividef(ea, 1.f + ea), zinv * ea));
        float cb = fmaf(w0, fmaxf(sb, 0.f), fmaf(w1, __fdividef(eb, 1.f + eb), zinv * eb));

        float vv[FDIM] = {v0.x, v0.y, v0.z, v0.w, v1.x, v1.y, v1.z, v1.w, v2.x, v2.y};
#pragma unroll
        for (int f = 0; f < FDIM; f++) {
            acc0[f] = fmaf(ca, vv[f], acc0[f]);
            acc1[f] = fmaf(cb, vv[f], acc1[f]);
        }
    }

    // out[t, f, h, w] with n = t*1024 + hw
    int t  = n >> 10;
    int hw = n & 1023;
    float* op = out + t * (FDIM * HW) + hw;
#pragma unroll
    for (int f = 0; f < FDIM; f++) atomicAdd(op + f * HW,     acc0[f]);
#pragma unroll
    for (int f = 0; f < FDIM; f++) atomicAdd(op + f * HW + 1, acc1[f]);
}

// ---------------------------------------------------------------------------
extern "C" void kernel_launch(void* const* d_in, const int* in_sizes, int n_in,
                              void* d_out, int out_size) {
    const float* in1 = (const float*)d_in[0];
    const float* in2 = (const float*)d_in[1];
    const float* aw  = (const float*)d_in[2];
    const float* w1  = (const float*)d_in[3];
    const float* b1  = (const float*)d_in[4];
    const float* w2  = (const float*)d_in[5];
    const float* b2  = (const float*)d_in[6];
    const float* w3  = (const float*)d_in[7];
    const float* b3  = (const float*)d_in[8];
    float* out = (float*)d_out;

    k_init<<<(OUT_ELEMS + 255) / 256, 256>>>(out);
    k_proj<<<N_TOK / 256, 256>>>(in1, in2, w1, b1, w2, b2, w3, b3);
    k_colsum<<<dim3(N_TOK / 256, SPLA), 256>>>();
    k_zinv<<<N_TOK / 256, 256>>>(aw);
    k_attn<<<dim3(N_TOK / 512, SPLB), 256>>>(aw, out);
}

// round 4
// speedup vs baseline: 1.3198x; 1.3198x over previous
#include <cuda_runtime.h>

// Shapes (fixed)
#define N_TOK 5120     // T*H*W = 5*32*32
#define FDIM  10
#define C_DIM 64
#define HW    1024
#define OUT_ELEMS 51200
#define NPAIR (N_TOK/2)

#define SPLA 64        // n-split for colsum
#define SPLB 64        // m-split for attn
#define L2E  1.44269504088896f

typedef unsigned long long u64;

// ---------------------------------------------------------------------------
// Scratch (device globals — allocation-free)
// g_qp  [2560][24] : paired q rows: [2f]=q[2p][f], [2f+1]=q[2p+1][f]  (pads unread)
// g_qd  [5120][20] : duplicated q, pre-scaled by log2(e): (q*L2E, q*L2E)
// g_kp  [2560][20] : paired k rows (for colsum, m-pairing)
// g_kvd [5120][48] : [0..19] dup k, [20..39] dup v, [40] Z (atomically built)
// g_stage [5120][12]: output accumulator, contiguous per token
__device__ float g_qp  [NPAIR * 24];
__device__ float g_qd  [N_TOK * 20];
__device__ float g_kp  [NPAIR * 20];
__device__ float g_kvd [N_TOK * 48];
__device__ float g_stage[N_TOK * 12];

// ---------------------------------------------------------------------------
// f32x2 / MUFU helpers
__device__ __forceinline__ u64 fma2(u64 a, u64 b, u64 c) {
    u64 d; asm("fma.rn.f32x2 %0, %1, %2, %3;" : "=l"(d) : "l"(a), "l"(b), "l"(c)); return d;
}
__device__ __forceinline__ u64 pk2(float lo, float hi) {
    u64 r; asm("mov.b64 %0, {%1, %2};" : "=l"(r) : "f"(lo), "f"(hi)); return r;
}
__device__ __forceinline__ float2 upk2(u64 v) {
    float2 r; asm("mov.b64 {%0, %1}, %2;" : "=f"(r.x), "=f"(r.y) : "l"(v)); return r;
}
__device__ __forceinline__ float ex2f(float x) {
    float r; asm("ex2.approx.ftz.f32 %0, %1;" : "=f"(r) : "f"(x)); return r;
}
__device__ __forceinline__ float rcpf(float x) {
    float r; asm("rcp.approx.ftz.f32 %0, %1;" : "=f"(r) : "f"(x)); return r;
}

// ---------------------------------------------------------------------------
__global__ void k_init(void) {
    int i = blockIdx.x * 256 + threadIdx.x;
    if (i < N_TOK * 12) g_stage[i] = 0.f;
    if (i < N_TOK)      g_kvd[i * 48 + 40] = 0.f;
}

// ---------------------------------------------------------------------------
// Projections + layout packing. One thread per token.
__global__ void k_proj(const float* __restrict__ in1, const float* __restrict__ in2,
                       const float* __restrict__ w1, const float* __restrict__ b1,
                       const float* __restrict__ w2, const float* __restrict__ b2,
                       const float* __restrict__ w3, const float* __restrict__ b3) {
    __shared__ float sw1[FDIM * C_DIM], sw2[FDIM * C_DIM], sw3[FDIM * C_DIM];
    int tid = threadIdx.x;
    for (int i = tid; i < FDIM * C_DIM; i += 256) {
        sw1[i] = w1[i]; sw2[i] = w2[i]; sw3[i] = w3[i];
    }
    __syncthreads();

    int n  = blockIdx.x * 256 + tid;
    int t  = n >> 10;
    int hw = n & 1023;
    const float* p1 = in1 + t * (C_DIM * HW) + hw;
    const float* p2 = in2 + t * (C_DIM * HW) + hw;

    float qa[FDIM], ka[FDIM], va[FDIM];
#pragma unroll
    for (int f = 0; f < FDIM; f++) { qa[f] = __ldg(b1 + f); ka[f] = __ldg(b2 + f); va[f] = __ldg(b3 + f); }

    for (int c = 0; c < C_DIM; c++) {
        float x1 = __ldg(p1 + c * HW);
        float x2 = __ldg(p2 + c * HW);
#pragma unroll
        for (int f = 0; f < FDIM; f++) {
            qa[f] = fmaf(sw1[f * C_DIM + c], x1, qa[f]);
            ka[f] = fmaf(sw2[f * C_DIM + c], x2, ka[f]);
            va[f] = fmaf(sw3[f * C_DIM + c], x1, va[f]);
        }
    }

    int p = n >> 1, h = n & 1;
    float* qp = g_qp  + p * 24;
    float* qd = g_qd  + n * 20;
    float* kp = g_kp  + p * 20;
    float* kv = g_kvd + n * 48;
#pragma unroll
    for (int f = 0; f < FDIM; f++) {
        qp[2 * f + h] = qa[f];
        float qs = qa[f] * L2E;
        qd[2 * f]     = qs;  qd[2 * f + 1] = qs;
        kp[2 * f + h] = ka[f];
        kv[2 * f]     = ka[f]; kv[2 * f + 1]  = ka[f];
        kv[20 + 2 * f] = va[f]; kv[21 + 2 * f] = va[f];
    }
}

// ---------------------------------------------------------------------------
// Pass A: Z[m] = sum_n exp(q_n . k_m).  Thread owns 4 m (2 m-pairs), loops
// an n-slice. qd rows are broadcast LDG.128; f32x2 dot; bare ex2 (q pre-scaled).
__global__ void __launch_bounds__(128) k_colsum(void) {
    int gt = blockIdx.x * 128 + threadIdx.x;    // 0..1279
    u64 ka[FDIM], kb[FDIM];
#pragma unroll
    for (int i = 0; i < 5; i++) {
        ulonglong2 t0 = __ldg((const ulonglong2*)(g_kp + (2 * gt)     * 20) + i);
        ulonglong2 t1 = __ldg((const ulonglong2*)(g_kp + (2 * gt + 1) * 20) + i);
        ka[2 * i] = t0.x; ka[2 * i + 1] = t0.y;
        kb[2 * i] = t1.x; kb[2 * i + 1] = t1.y;
    }

    int n0 = blockIdx.y * (N_TOK / SPLA);
    float z0 = 0.f, z1 = 0.f, z2 = 0.f, z3 = 0.f;
    for (int n = n0; n < n0 + N_TOK / SPLA; n++) {
        const ulonglong2* qr = (const ulonglong2*)(g_qd + n * 20);
        u64 q[FDIM];
#pragma unroll
        for (int i = 0; i < 5; i++) { ulonglong2 v = __ldg(qr + i); q[2 * i] = v.x; q[2 * i + 1] = v.y; }
        u64 sA = 0ull, sB = 0ull;
#pragma unroll
        for (int f = 0; f < FDIM; f++) { sA = fma2(q[f], ka[f], sA); sB = fma2(q[f], kb[f], sB); }
        float2 a = upk2(sA), b = upk2(sB);
        z0 += ex2f(a.x); z1 += ex2f(a.y); z2 += ex2f(b.x); z3 += ex2f(b.y);
    }
    atomicAdd(&g_kvd[(4 * gt + 0) * 48 + 40], z0);
    atomicAdd(&g_kvd[(4 * gt + 1) * 48 + 40], z1);
    atomicAdd(&g_kvd[(4 * gt + 2) * 48 + 40], z2);
    atomicAdd(&g_kvd[(4 * gt + 3) * 48 + 40], z3);
}

// ---------------------------------------------------------------------------
// Pass B: fused relu/sigmoid/softmax. Thread owns 4 n (2 q-pairs), loops an
// m-slice. k/v arrive pre-duplicated -> pure f32x2 FMA stream; zinv computed
// inline from Z (folds old k_zinv kernel). Vector atomics into g_stage.
__global__ void __launch_bounds__(128, 3) k_attn(const float* __restrict__ aw) {
    int tid = blockIdx.x * 128 + threadIdx.x;   // 0..1279
    int n0  = tid * 4;
    float w0 = __ldg(aw), w1 = __ldg(aw + 1);

    u64 qA[FDIM], qB[FDIM];
#pragma unroll
    for (int i = 0; i < 5; i++) {
        ulonglong2 t0 = __ldg((const ulonglong2*)(g_qp + (2 * tid)     * 24) + i);
        ulonglong2 t1 = __ldg((const ulonglong2*)(g_qp + (2 * tid + 1) * 24) + i);
        qA[2 * i] = t0.x; qA[2 * i + 1] = t0.y;
        qB[2 * i] = t1.x; qB[2 * i + 1] = t1.y;
    }

    u64 acc0[FDIM], acc1[FDIM];
#pragma unroll
    for (int f = 0; f < FDIM; f++) { acc0[f] = 0ull; acc1[f] = 0ull; }

    int m0 = blockIdx.y * (N_TOK / SPLB);
    for (int m = m0; m < m0 + N_TOK / SPLB; m++) {
        const float* row = g_kvd + m * 48;
        u64 kd[FDIM], vd[FDIM];
#pragma unroll
        for (int i = 0; i < 5; i++) {
            ulonglong2 k2 = __ldg((const ulonglong2*)row + i);
            ulonglong2 v2 = __ldg((const ulonglong2*)(row + 20) + i);
            kd[2 * i] = k2.x; kd[2 * i + 1] = k2.y;
            vd[2 * i] = v2.x; vd[2 * i + 1] = v2.y;
        }
        float zinv = w0 * rcpf(__ldg(row + 40));

        u64 sA = 0ull, sB = 0ull;
#pragma unroll
        for (int f = 0; f < FDIM; f++) { sA = fma2(qA[f], kd[f], sA); sB = fma2(qB[f], kd[f], sB); }
        float2 a = upk2(sA), b = upk2(sB);

        // coef(s) = w0*relu(s) + e*(w1*rcp(1+e) + zinv),  e = exp(s)
        float e0 = ex2f(a.x * L2E), e1 = ex2f(a.y * L2E);
        float e2 = ex2f(b.x * L2E), e3 = ex2f(b.y * L2E);
        float c0 = fmaf(w0, fmaxf(a.x, 0.f), e0 * fmaf(w1, rcpf(1.f + e0), zinv));
        float c1 = fmaf(w0, fmaxf(a.y, 0.f), e1 * fmaf(w1, rcpf(1.f + e1), zinv));
        float c2 = fmaf(w0, fmaxf(b.x, 0.f), e2 * fmaf(w1, rcpf(1.f + e2), zinv));
        float c3 = fmaf(w0, fmaxf(b.y, 0.f), e3 * fmaf(w1, rcpf(1.f + e3), zinv));
        u64 cA = pk2(c0, c1), cB = pk2(c2, c3);
#pragma unroll
        for (int f = 0; f < FDIM; f++) {
            acc0[f] = fma2(cA, vd[f], acc0[f]);
            acc1[f] = fma2(cB, vd[f], acc1[f]);
        }
    }

    // Stage reduction: contiguous per-token rows -> vector atomics (v4+v4+v2)
    float2 u0[FDIM], u1[FDIM];
#pragma unroll
    for (int f = 0; f < FDIM; f++) { u0[f] = upk2(acc0[f]); u1[f] = upk2(acc1[f]); }

    float* s0 = g_stage + (n0 + 0) * 12;
    float* s1 = g_stage + (n0 + 1) * 12;
    float* s2 = g_stage + (n0 + 2) * 12;
    float* s3 = g_stage + (n0 + 3) * 12;
    atomicAdd((float4*)(s0),     make_float4(u0[0].x, u0[1].x, u0[2].x, u0[3].x));
    atomicAdd((float4*)(s0 + 4), make_float4(u0[4].x, u0[5].x, u0[6].x, u0[7].x));
    atomicAdd((float2*)(s0 + 8), make_float2(u0[8].x, u0[9].x));
    atomicAdd((float4*)(s1),     make_float4(u0[0].y, u0[1].y, u0[2].y, u0[3].y));
    atomicAdd((float4*)(s1 + 4), make_float4(u0[4].y, u0[5].y, u0[6].y, u0[7].y));
    atomicAdd((float2*)(s1 + 8), make_float2(u0[8].y, u0[9].y));
    atomicAdd((float4*)(s2),     make_float4(u1[0].x, u1[1].x, u1[2].x, u1[3].x));
    atomicAdd((float4*)(s2 + 4), make_float4(u1[4].x, u1[5].x, u1[6].x, u1[7].x));
    atomicAdd((float2*)(s2 + 8), make_float2(u1[8].x, u1[9].x));
    atomicAdd((float4*)(s3),     make_float4(u1[0].y, u1[1].y, u1[2].y, u1[3].y));
    atomicAdd((float4*)(s3 + 4), make_float4(u1[4].y, u1[5].y, u1[6].y, u1[7].y));
    atomicAdd((float2*)(s3 + 8), make_float2(u1[8].y, u1[9].y));
}

// ---------------------------------------------------------------------------
// Transpose stage -> out[t][f][hw]
__global__ void k_final(float* __restrict__ out) {
    int i = blockIdx.x * 256 + threadIdx.x;     // 0..51199
    int t  = i / (FDIM * HW);
    int r  = i - t * (FDIM * HW);
    int f  = r >> 10;
    int hw = r & 1023;
    out[i] = g_stage[(t * HW + hw) * 12 + f];
}

// ---------------------------------------------------------------------------
extern "C" void kernel_launch(void* const* d_in, const int* in_sizes, int n_in,
                              void* d_out, int out_size) {
    const float* in1 = (const float*)d_in[0];
    const float* in2 = (const float*)d_in[1];
    const float* aw  = (const float*)d_in[2];
    const float* w1  = (const float*)d_in[3];
    const float* b1  = (const float*)d_in[4];
    const float* w2  = (const float*)d_in[5];
    const float* b2  = (const float*)d_in[6];
    const float* w3  = (const float*)d_in[7];
    const float* b3  = (const float*)d_in[8];
    float* out = (float*)d_out;

    k_init  <<<240, 256>>>();                                      // idx 0
    k_proj  <<<N_TOK / 256, 256>>>(in1, in2, w1, b1, w2, b2, w3, b3); // idx 1
    k_colsum<<<dim3(10, SPLA), 128>>>();                           // idx 2
    k_attn  <<<dim3(10, SPLB), 128>>>(aw);                         // idx 3  (ncu capture slot)
    k_final <<<OUT_ELEMS / 256, 256>>>(out);                       // idx 4
}

// round 5
// speedup vs baseline: 2.0643x; 1.5641x over previous
#include <cuda_runtime.h>

// Shapes (fixed)
#define N_TOK 5120     // T*H*W = 5*32*32
#define FDIM  10
#define C_DIM 64
#define HW    1024
#define OUT_ELEMS 51200
#define NPAIR (N_TOK/2)

#define SPLA 128       // n-split for colsum (slice = 40)
#define SPLB 64        // m-split for attn   (slice = 80)
#define MSL  80        // attn m-slice per block
#define NSL  40        // colsum n-slice per block
#define L2E  1.44269504088896f

typedef unsigned long long u64;

// ---------------------------------------------------------------------------
// Scratch (device globals — allocation-free)
// g_qp  [2560][24] : paired q rows (PRE-SCALED by log2e): [2f]=q'[2p][f], [2f+1]=q'[2p+1][f]
// g_qd  [5120][20] : duplicated q, pre-scaled by log2e: (q', q')
// g_kp  [2560][20] : paired k rows (colsum m-pairing)
// g_kvd [5120][48] : [0..19] dup k, [20..39] dup v, [40] Z (atomically built)
// g_stage [5120][12]: output accumulator, contiguous per token
__device__ float g_qp  [NPAIR * 24];
__device__ float g_qd  [N_TOK * 20];
__device__ float g_kp  [NPAIR * 20];
__device__ float g_kvd [N_TOK * 48];
__device__ float g_stage[N_TOK * 12];

// ---------------------------------------------------------------------------
__device__ __forceinline__ u64 fma2(u64 a, u64 b, u64 c) {
    u64 d; asm("fma.rn.f32x2 %0, %1, %2, %3;" : "=l"(d) : "l"(a), "l"(b), "l"(c)); return d;
}
__device__ __forceinline__ u64 add2(u64 a, u64 b) {
    u64 d; asm("add.rn.f32x2 %0, %1, %2;" : "=l"(d) : "l"(a), "l"(b)); return d;
}
__device__ __forceinline__ u64 pk2(float lo, float hi) {
    u64 r; asm("mov.b64 %0, {%1, %2};" : "=l"(r) : "f"(lo), "f"(hi)); return r;
}
__device__ __forceinline__ float2 upk2(u64 v) {
    float2 r; asm("mov.b64 {%0, %1}, %2;" : "=f"(r.x), "=f"(r.y) : "l"(v)); return r;
}
__device__ __forceinline__ float ex2f(float x) {
    float r; asm("ex2.approx.ftz.f32 %0, %1;" : "=f"(r) : "f"(x)); return r;
}
__device__ __forceinline__ float rcpf(float x) {
    float r; asm("rcp.approx.ftz.f32 %0, %1;" : "=f"(r) : "f"(x)); return r;
}

// ---------------------------------------------------------------------------
__global__ void k_init(void) {
    int i = blockIdx.x * 256 + threadIdx.x;
    if (i < N_TOK * 12) g_stage[i] = 0.f;
    if (i < N_TOK)      g_kvd[i * 48 + 40] = 0.f;
}

// ---------------------------------------------------------------------------
// Projections + layout packing. One thread per token; 80 blocks x 64 threads.
__global__ void k_proj(const float* __restrict__ in1, const float* __restrict__ in2,
                       const float* __restrict__ w1, const float* __restrict__ b1,
                       const float* __restrict__ w2, const float* __restrict__ b2,
                       const float* __restrict__ w3, const float* __restrict__ b3) {
    __shared__ float sw1[FDIM * C_DIM], sw2[FDIM * C_DIM], sw3[FDIM * C_DIM];
    int tid = threadIdx.x;
    for (int i = tid; i < FDIM * C_DIM; i += 64) {
        sw1[i] = w1[i]; sw2[i] = w2[i]; sw3[i] = w3[i];
    }
    __syncthreads();

    int n  = blockIdx.x * 64 + tid;
    int t  = n >> 10;
    int hw = n & 1023;
    const float* p1 = in1 + t * (C_DIM * HW) + hw;
    const float* p2 = in2 + t * (C_DIM * HW) + hw;

    float qa[FDIM], ka[FDIM], va[FDIM];
#pragma unroll
    for (int f = 0; f < FDIM; f++) { qa[f] = __ldg(b1 + f); ka[f] = __ldg(b2 + f); va[f] = __ldg(b3 + f); }

    for (int c = 0; c < C_DIM; c++) {
        float x1 = __ldg(p1 + c * HW);
        float x2 = __ldg(p2 + c * HW);
#pragma unroll
        for (int f = 0; f < FDIM; f++) {
            qa[f] = fmaf(sw1[f * C_DIM + c], x1, qa[f]);
            ka[f] = fmaf(sw2[f * C_DIM + c], x2, ka[f]);
            va[f] = fmaf(sw3[f * C_DIM + c], x1, va[f]);
        }
    }

    int p = n >> 1, h = n & 1;
    float* qp = g_qp  + p * 24;
    float* qd = g_qd  + n * 20;
    float* kp = g_kp  + p * 20;
    float* kv = g_kvd + n * 48;
#pragma unroll
    for (int f = 0; f < FDIM; f++) {
        float qs = qa[f] * L2E;              // pre-scale by log2(e)
        qp[2 * f + h] = qs;
        qd[2 * f]     = qs;  qd[2 * f + 1]  = qs;
        kp[2 * f + h] = ka[f];
        kv[2 * f]      = ka[f]; kv[2 * f + 1]  = ka[f];
        kv[20 + 2 * f] = va[f]; kv[21 + 2 * f] = va[f];
    }
}

// ---------------------------------------------------------------------------
// Pass A: Z[m] = sum_n exp(q_n . k_m).
// Thread owns 8 m (4 m-pairs, k in regs); block stages an n-slice of dup-q
// rows in smem. grid (5, SPLA), 128 threads.
__global__ void __launch_bounds__(128, 4) k_colsum(void) {
    __shared__ __align__(16) float sq[NSL * 20];
    int tid = threadIdx.x;
    int gt  = blockIdx.x * 128 + tid;            // 0..639
    int n0  = blockIdx.y * NSL;

    // stage q slice: NSL rows x 5 float4
    for (int i = tid; i < NSL * 5; i += 128) {
        int r = i / 5, c = i - r * 5;
        ((float4*)sq)[r * 5 + c] = __ldg((const float4*)(g_qd + (n0 + r) * 20) + c);
    }
    __syncthreads();

    // 4 m-pair k rows in registers
    u64 ka[4][FDIM];
#pragma unroll
    for (int p = 0; p < 4; p++) {
        const ulonglong2* kr = (const ulonglong2*)(g_kp + (4 * gt + p) * 20);
#pragma unroll
        for (int i = 0; i < 5; i++) {
            ulonglong2 v = __ldg(kr + i);
            ka[p][2 * i] = v.x; ka[p][2 * i + 1] = v.y;
        }
    }

    float z[8];
#pragma unroll
    for (int i = 0; i < 8; i++) z[i] = 0.f;

    for (int nn = 0; nn < NSL; nn++) {
        const ulonglong2* qr = (const ulonglong2*)(sq + nn * 20);
        u64 q[FDIM];
#pragma unroll
        for (int i = 0; i < 5; i++) { ulonglong2 v = qr[i]; q[2 * i] = v.x; q[2 * i + 1] = v.y; }
#pragma unroll
        for (int p = 0; p < 4; p++) {
            u64 s0 = 0ull, s1 = 0ull;
#pragma unroll
            for (int i = 0; i < 5; i++) {
                s0 = fma2(q[2 * i],     ka[p][2 * i],     s0);
                s1 = fma2(q[2 * i + 1], ka[p][2 * i + 1], s1);
            }
            float2 s = upk2(add2(s0, s1));
            z[2 * p]     += ex2f(s.x);
            z[2 * p + 1] += ex2f(s.y);
        }
    }
#pragma unroll
    for (int i = 0; i < 8; i++)
        atomicAdd(&g_kvd[(8 * gt + i) * 48 + 40], z[i]);
}

// ---------------------------------------------------------------------------
// Pass B: fused relu/sigmoid/softmax. Thread owns 4 n (2 prescaled q-pairs);
// block stages an m-slice of dup k/v + zinv in smem. grid (10, SPLB), 128 thr.
__global__ void __launch_bounds__(128, 4) k_attn(const float* __restrict__ aw) {
    __shared__ __align__(16) float skv[MSL * 40];
    __shared__ float szinv[MSL];
    int tid = threadIdx.x;
    int gt  = blockIdx.x * 128 + tid;            // 0..1279
    int m0  = blockIdx.y * MSL;
    float w0 = __ldg(aw), w1 = __ldg(aw + 1);
    float w0r = w0 * (1.0f / L2E);               // relu on prescaled scores

    // stage k/v slice: MSL rows x 10 float4 (k dup + v dup), plus zinv
    for (int i = tid; i < MSL * 10; i += 128) {
        int r = i / 10, c = i - r * 10;
        ((float4*)skv)[r * 10 + c] = __ldg((const float4*)(g_kvd + (m0 + r) * 48) + c);
    }
    if (tid < MSL) szinv[tid] = w0 * rcpf(g_kvd[(m0 + tid) * 48 + 40]);
    __syncthreads();

    u64 qA[FDIM], qB[FDIM];
#pragma unroll
    for (int i = 0; i < 5; i++) {
        ulonglong2 t0 = __ldg((const ulonglong2*)(g_qp + (2 * gt)     * 24) + i);
        ulonglong2 t1 = __ldg((const ulonglong2*)(g_qp + (2 * gt + 1) * 24) + i);
        qA[2 * i] = t0.x; qA[2 * i + 1] = t0.y;
        qB[2 * i] = t1.x; qB[2 * i + 1] = t1.y;
    }

    u64 acc0[FDIM], acc1[FDIM];
#pragma unroll
    for (int f = 0; f < FDIM; f++) { acc0[f] = 0ull; acc1[f] = 0ull; }

    for (int mm = 0; mm < MSL; mm++) {
        const float* row = skv + mm * 40;
        float zinv = szinv[mm];

        // dot phase: k loads + two 5-deep chains per score pair
        u64 sA0 = 0ull, sA1 = 0ull, sB0 = 0ull, sB1 = 0ull;
#pragma unroll
        for (int i = 0; i < 5; i++) {
            ulonglong2 kk = ((const ulonglong2*)row)[i];
            sA0 = fma2(qA[2 * i],     kk.x, sA0);
            sA1 = fma2(qA[2 * i + 1], kk.y, sA1);
            sB0 = fma2(qB[2 * i],     kk.x, sB0);
            sB1 = fma2(qB[2 * i + 1], kk.y, sB1);
        }
        float2 a = upk2(add2(sA0, sA1));
        float2 b = upk2(add2(sB0, sB1));

        // coef(s') = w0r*max(s',0) + e*(w1*rcp(1+e) + zinv),  e = ex2(s')
        float e0 = ex2f(a.x), e1 = ex2f(a.y), e2 = ex2f(b.x), e3 = ex2f(b.y);
        float c0 = fmaf(e0, fmaf(w1, rcpf(1.f + e0), zinv), w0r * fmaxf(a.x, 0.f));
        float c1 = fmaf(e1, fmaf(w1, rcpf(1.f + e1), zinv), w0r * fmaxf(a.y, 0.f));
        float c2 = fmaf(e2, fmaf(w1, rcpf(1.f + e2), zinv), w0r * fmaxf(b.x, 0.f));
        float c3 = fmaf(e3, fmaf(w1, rcpf(1.f + e3), zinv), w0r * fmaxf(b.y, 0.f));
        u64 cA = pk2(c0, c1), cB = pk2(c2, c3);

        // acc phase: v loads + independent accumulators
#pragma unroll
        for (int i = 0; i < 5; i++) {
            ulonglong2 vv = ((const ulonglong2*)(row + 20))[i];
            acc0[2 * i]     = fma2(cA, vv.x, acc0[2 * i]);
            acc0[2 * i + 1] = fma2(cA, vv.y, acc0[2 * i + 1]);
            acc1[2 * i]     = fma2(cB, vv.x, acc1[2 * i]);
            acc1[2 * i + 1] = fma2(cB, vv.y, acc1[2 * i + 1]);
        }
    }

    // stage reduction: contiguous per-token rows -> vector atomics
    float2 u0[FDIM], u1[FDIM];
#pragma unroll
    for (int f = 0; f < FDIM; f++) { u0[f] = upk2(acc0[f]); u1[f] = upk2(acc1[f]); }

    int n0 = gt * 4;
    float* s0 = g_stage + (n0 + 0) * 12;
    float* s1 = g_stage + (n0 + 1) * 12;
    float* s2 = g_stage + (n0 + 2) * 12;
    float* s3 = g_stage + (n0 + 3) * 12;
    atomicAdd((float4*)(s0),     make_float4(u0[0].x, u0[1].x, u0[2].x, u0[3].x));
    atomicAdd((float4*)(s0 + 4), make_float4(u0[4].x, u0[5].x, u0[6].x, u0[7].x));
    atomicAdd((float2*)(s0 + 8), make_float2(u0[8].x, u0[9].x));
    atomicAdd((float4*)(s1),     make_float4(u0[0].y, u0[1].y, u0[2].y, u0[3].y));
    atomicAdd((float4*)(s1 + 4), make_float4(u0[4].y, u0[5].y, u0[6].y, u0[7].y));
    atomicAdd((float2*)(s1 + 8), make_float2(u0[8].y, u0[9].y));
    atomicAdd((float4*)(s2),     make_float4(u1[0].x, u1[1].x, u1[2].x, u1[3].x));
    atomicAdd((float4*)(s2 + 4), make_float4(u1[4].x, u1[5].x, u1[6].x, u1[7].x));
    atomicAdd((float2*)(s2 + 8), make_float2(u1[8].x, u1[9].x));
    atomicAdd((float4*)(s3),     make_float4(u1[0].y, u1[1].y, u1[2].y, u1[3].y));
    atomicAdd((float4*)(s3 + 4), make_float4(u1[4].y, u1[5].y, u1[6].y, u1[7].y));
    atomicAdd((float2*)(s3 + 8), make_float2(u1[8].y, u1[9].y));
}

// ---------------------------------------------------------------------------
// Transpose stage -> out[t][f][hw]
__global__ void k_final(float* __restrict__ out) {
    int i = blockIdx.x * 256 + threadIdx.x;     // 0..51199
    int t  = i / (FDIM * HW);
    int r  = i - t * (FDIM * HW);
    int f  = r >> 10;
    int hw = r & 1023;
    out[i] = g_stage[(t * HW + hw) * 12 + f];
}

// ---------------------------------------------------------------------------
extern "C" void kernel_launch(void* const* d_in, const int* in_sizes, int n_in,
                              void* d_out, int out_size) {
    const float* in1 = (const float*)d_in[0];
    const float* in2 = (const float*)d_in[1];
    const float* aw  = (const float*)d_in[2];
    const float* w1  = (const float*)d_in[3];
    const float* b1  = (const float*)d_in[4];
    const float* w2  = (const float*)d_in[5];
    const float* b2  = (const float*)d_in[6];
    const float* w3  = (const float*)d_in[7];
    const float* b3  = (const float*)d_in[8];
    float* out = (float*)d_out;

    k_init  <<<240, 256>>>();                                         // idx 0
    k_proj  <<<N_TOK / 64, 64>>>(in1, in2, w1, b1, w2, b2, w3, b3);   // idx 1
    k_colsum<<<dim3(5, SPLA), 128>>>();                               // idx 2
    k_attn  <<<dim3(10, SPLB), 128>>>(aw);                            // idx 3  (capture slot)
    k_final <<<OUT_ELEMS / 256, 256>>>(out);                          // idx 4
}